// round 15
// baseline (speedup 1.0000x reference)
#include <cuda_runtime.h>
#include <cuda_bf16.h>
#include <cstdint>

#define NUM_USERS 50000
#define NUM_ITEMS 10000
#define NUM_SUPPORT 5
#define INPUT_DIM 512
#define OUTPUT_DIM 500
#define NNZ 400000
#define HIDDEN 100
#define N_PAD 512

// ---------------- scratch (device globals: no allocation) ----------------
__device__ float g_tmp_u[(size_t)NUM_USERS * OUTPUT_DIM];            // 100 MB
__device__ float g_tmp_v[(size_t)NUM_ITEMS * OUTPUT_DIM];            //  20 MB
__device__ __nv_bfloat16 g_Bh[(size_t)INPUT_DIM * N_PAD];            // 0.5 MB
__device__ __nv_bfloat16 g_Bl[(size_t)INPUT_DIM * N_PAD];            // 0.5 MB
__device__ __nv_bfloat16 g_Ah_u[(size_t)NUM_USERS * INPUT_DIM];      // 51 MB
__device__ __nv_bfloat16 g_Al_u[(size_t)NUM_USERS * INPUT_DIM];      // 51 MB
__device__ __nv_bfloat16 g_Ah_v[(size_t)NUM_ITEMS * INPUT_DIM];      // 10 MB
__device__ __nv_bfloat16 g_Al_v[(size_t)NUM_ITEMS * INPUT_DIM];      // 10 MB

// CSR build scratch
__device__ int  g_cnt_u[NUM_SUPPORT * NUM_USERS];
__device__ int  g_cnt_v[NUM_SUPPORT * NUM_ITEMS];
__device__ int  g_off_u[NUM_SUPPORT * (NUM_USERS + 1)];
__device__ int  g_off_v[NUM_SUPPORT * (NUM_ITEMS + 1)];
__device__ int  g_cur_u[NUM_SUPPORT * NUM_USERS];
__device__ int  g_cur_v[NUM_SUPPORT * NUM_ITEMS];
__device__ int2 g_edges_u[(size_t)NUM_SUPPORT * NNZ];                // 16 MB
__device__ int2 g_edges_v[(size_t)NUM_SUPPORT * NNZ];                // 16 MB

// ---------------- GEMM tiling ----------------
// CTA 128M x 128N, 8 warps (4x2), warp tile 32x64. K'=1536, 24 chunks of 64.
// 3-stage cp.async pipeline, one __syncthreads per chunk.
#define A_BYTES (128 * 144)
#define B_BYTES (64 * 272)
#define BUF_BYTES (A_BYTES + B_BYTES)          // 35840
#define NSTAGE 3
#define GEMM_SMEM (NSTAGE * BUF_BYTES)         // 107520
#define NCHUNK 24

__device__ __forceinline__ uint32_t smem_u32(const void* p) {
    uint32_t a;
    asm("{ .reg .u64 t; cvta.to.shared.u64 t, %1; cvt.u32.u64 %0, t; }" : "=r"(a) : "l"(p));
    return a;
}

__device__ __forceinline__ uint32_t bf2_hi(float x, float y) {
    unsigned short a = __bfloat16_as_ushort(__float2bfloat16_rn(x));
    unsigned short b = __bfloat16_as_ushort(__float2bfloat16_rn(y));
    return (uint32_t)a | ((uint32_t)b << 16);
}
__device__ __forceinline__ uint32_t bf2_lo(float x, float y) {
    float hx = __bfloat162float(__float2bfloat16_rn(x));
    float hy = __bfloat162float(__float2bfloat16_rn(y));
    unsigned short a = __bfloat16_as_ushort(__float2bfloat16_rn(x - hx));
    unsigned short b = __bfloat16_as_ushort(__float2bfloat16_rn(y - hy));
    return (uint32_t)a | ((uint32_t)b << 16);
}

__device__ __forceinline__ void ldsm_x4(uint32_t* r, uint32_t addr) {
    asm volatile("ldmatrix.sync.aligned.m8n8.x4.shared.b16 {%0,%1,%2,%3}, [%4];"
                 : "=r"(r[0]), "=r"(r[1]), "=r"(r[2]), "=r"(r[3]) : "r"(addr));
}
__device__ __forceinline__ void ldsm_x4_t(uint32_t* r, uint32_t addr) {
    asm volatile("ldmatrix.sync.aligned.m8n8.x4.trans.shared.b16 {%0,%1,%2,%3}, [%4];"
                 : "=r"(r[0]), "=r"(r[1]), "=r"(r[2]), "=r"(r[3]) : "r"(addr));
}
__device__ __forceinline__ void mma16816(float* d, const uint32_t* a,
                                         uint32_t b0, uint32_t b1) {
    asm volatile(
        "mma.sync.aligned.m16n8k16.row.col.f32.bf16.bf16.f32 "
        "{%0,%1,%2,%3}, {%4,%5,%6,%7}, {%8,%9}, {%0,%1,%2,%3};"
        : "+f"(d[0]), "+f"(d[1]), "+f"(d[2]), "+f"(d[3])
        : "r"(a[0]), "r"(a[1]), "r"(a[2]), "r"(a[3]), "r"(b0), "r"(b1));
}
__device__ __forceinline__ void cp16(uint32_t dst, const void* src, int srcsize) {
    asm volatile("cp.async.cg.shared.global [%0], [%1], 16, %2;"
                 :: "r"(dst), "l"(src), "r"(srcsize) : "memory");
}

// ---------------------------------------------------------------------------
__global__ __launch_bounds__(256)
void prep_b_kernel(const float* __restrict__ W,
                   __nv_bfloat16* __restrict__ Bh, __nv_bfloat16* __restrict__ Bl) {
    int idx = blockIdx.x * 256 + threadIdx.x;
    if (idx >= INPUT_DIM * N_PAD) return;
    int k = idx >> 9;
    int n = idx & (N_PAD - 1);
    float w = (n < OUTPUT_DIM) ? W[(size_t)k * OUTPUT_DIM + n] : 0.0f;
    __nv_bfloat16 h = __float2bfloat16_rn(w);
    Bh[idx] = h;
    Bl[idx] = __float2bfloat16_rn(w - __bfloat162float(h));
}

__global__ __launch_bounds__(256)
void split_a_kernel(const float4* __restrict__ A,
                    uint2* __restrict__ Ah, uint2* __restrict__ Al, int n4) {
    int idx = blockIdx.x * 256 + threadIdx.x;
    if (idx >= n4) return;
    float4 v = A[idx];
    uint2 h, l;
    h.x = bf2_hi(v.x, v.y); h.y = bf2_hi(v.z, v.w);
    l.x = bf2_lo(v.x, v.y); l.y = bf2_lo(v.z, v.w);
    Ah[idx] = h;
    Al[idx] = l;
}

// ---------------------------------------------------------------------------
// GEMM: bf16 3-stage pipeline (cp.async -> ldmatrix -> mma), K'=1536.
// ---------------------------------------------------------------------------
__global__ __launch_bounds__(256)
void gemm_mma_kernel(const __nv_bfloat16* __restrict__ Ah,
                     const __nv_bfloat16* __restrict__ Al,
                     const __nv_bfloat16* __restrict__ Bh,
                     const __nv_bfloat16* __restrict__ Bl,
                     float* __restrict__ C, int M) {
    extern __shared__ __align__(16) char smem[];
    const uint32_t sbase = smem_u32(smem);

    const int tid  = threadIdx.x;
    const int lane = tid & 31;
    const int wid  = tid >> 5;
    const int wm   = wid & 3;
    const int wn   = wid >> 2;

    const int row0 = blockIdx.y * 128;
    const int n0   = blockIdx.x * 128;

    auto issue = [&](int c) {
        const int region = c >> 3;                  // 0:(Ah,Bh) 1:(Al,Bh) 2:(Ah,Bl)
        const int k0 = (c & 7) * 64;
        const __nv_bfloat16* At = (region == 1) ? Al : Ah;
        const __nv_bfloat16* Bt = (region == 2) ? Bl : Bh;
        const uint32_t abuf = sbase + (c % NSTAGE) * BUF_BYTES;
        const uint32_t bbuf = abuf + A_BYTES;
#pragma unroll
        for (int i = 0; i < 4; i++) {
            const int s = tid + i * 256;
            const int ar = s >> 3;
            const int ao = s & 7;
            const int gm = row0 + ar;
            cp16(abuf + ar * 144 + ao * 16,
                 At + (size_t)gm * INPUT_DIM + k0 + ao * 8,
                 (gm < M) ? 16 : 0);
        }
#pragma unroll
        for (int i = 0; i < 4; i++) {
            const int s = tid + i * 256;
            const int br = s >> 4;
            const int bo = s & 15;
            cp16(bbuf + br * 272 + bo * 16,
                 Bt + (size_t)(k0 + br) * N_PAD + n0 + bo * 8, 16);
        }
        asm volatile("cp.async.commit_group;" ::: "memory");
    };

    float acc[2][8][4];
#pragma unroll
    for (int i = 0; i < 2; i++)
#pragma unroll
        for (int j = 0; j < 8; j++)
#pragma unroll
            for (int q = 0; q < 4; q++) acc[i][j][q] = 0.0f;

    const uint32_t a_lane_off =
        (uint32_t)((wm * 32 + (lane & 15)) * 144 + (lane >> 4) * 16);
    const uint32_t b_lane_off =
        (uint32_t)((lane & 15) * 272 + (wn * 64 + (lane >> 4) * 8) * 2);

    issue(0);
    issue(1);

    for (int c = 0; c < NCHUNK; c++) {
        if (c == NCHUNK - 1) {
            asm volatile("cp.async.wait_group 0;" ::: "memory");
        } else {
            asm volatile("cp.async.wait_group 1;" ::: "memory");
        }
        __syncthreads();

        // prefetch chunk c+2 into the buffer consumed at iter c-1
        if (c + 2 < NCHUNK) issue(c + 2);

        const uint32_t abase = sbase + (c % NSTAGE) * BUF_BYTES + a_lane_off;
        const uint32_t bbase = sbase + (c % NSTAGE) * BUF_BYTES + A_BYTES + b_lane_off;

#pragma unroll
        for (int ks = 0; ks < 4; ks++) {
            uint32_t a0[4], a1[4];
            ldsm_x4(a0, abase + ks * 32);
            ldsm_x4(a1, abase + 16 * 144 + ks * 32);
            uint32_t b[4][4];
#pragma unroll
            for (int q = 0; q < 4; q++)
                ldsm_x4_t(b[q], bbase + ks * 16 * 272 + q * 32);
#pragma unroll
            for (int j = 0; j < 8; j++) {
                const int q = j >> 1;
                const int h = (j & 1) * 2;
                mma16816(acc[0][j], a0, b[q][h], b[q][h + 1]);
                mma16816(acc[1][j], a1, b[q][h], b[q][h + 1]);
            }
        }
    }

    // ---- epilogue ----
#pragma unroll
    for (int i = 0; i < 2; i++) {
#pragma unroll
        for (int j = 0; j < 8; j++) {
            const int col = n0 + wn * 64 + j * 8 + (lane & 3) * 2;
            if (col >= OUTPUT_DIM) continue;
            const int r0 = row0 + wm * 32 + i * 16 + (lane >> 2);
            if (r0 < M) {
                float2 v = make_float2(acc[i][j][0], acc[i][j][1]);
                *reinterpret_cast<float2*>(&C[(size_t)r0 * OUTPUT_DIM + col]) = v;
            }
            if (r0 + 8 < M) {
                float2 v = make_float2(acc[i][j][2], acc[i][j][3]);
                *reinterpret_cast<float2*>(&C[(size_t)(r0 + 8) * OUTPUT_DIM + col]) = v;
            }
        }
    }
}

// ---------------------------------------------------------------------------
// CSR build: histogram -> scan -> fill
// ---------------------------------------------------------------------------
__global__ __launch_bounds__(256)
void hist_kernel(const int* __restrict__ sup_rows, const int* __restrict__ sup_cols) {
    const int e = blockIdx.x * 256 + threadIdx.x;
    if (e >= NUM_SUPPORT * NNZ) return;
    const int s = e / NNZ;
    atomicAdd(&g_cnt_u[s * NUM_USERS + sup_rows[e]], 1);
    atomicAdd(&g_cnt_v[s * NUM_ITEMS + sup_cols[e]], 1);
}

__global__ __launch_bounds__(512)
void scan_kernel() {
    const int aid = blockIdx.x;
    const int* cnt;
    int* off;
    int* cur;
    int n;
    if (aid < NUM_SUPPORT) {
        cnt = g_cnt_u + aid * NUM_USERS;
        off = g_off_u + aid * (NUM_USERS + 1);
        cur = g_cur_u + aid * NUM_USERS;
        n = NUM_USERS;
    } else {
        const int s = aid - NUM_SUPPORT;
        cnt = g_cnt_v + s * NUM_ITEMS;
        off = g_off_v + s * (NUM_ITEMS + 1);
        cur = g_cur_v + s * NUM_ITEMS;
        n = NUM_ITEMS;
    }

    __shared__ int warp_sums[16];
    __shared__ int carry_s;
    const int tid = threadIdx.x;
    const int lane = tid & 31;
    const int wrp = tid >> 5;
    if (tid == 0) carry_s = 0;
    __syncthreads();

    for (int base = 0; base < n; base += 512) {
        const int i = base + tid;
        const int x = (i < n) ? cnt[i] : 0;
        int v = x;
#pragma unroll
        for (int d = 1; d < 32; d <<= 1) {
            int t = __shfl_up_sync(0xffffffffu, v, d);
            if (lane >= d) v += t;
        }
        if (lane == 31) warp_sums[wrp] = v;
        __syncthreads();
        if (tid < 16) {
            int w = warp_sums[tid];
#pragma unroll
            for (int d = 1; d < 16; d <<= 1) {
                int t = __shfl_up_sync(0x0000ffffu, w, d);
                if (tid >= d) w += t;
            }
            warp_sums[tid] = w;
        }
        __syncthreads();
        const int warp_off = (wrp > 0) ? warp_sums[wrp - 1] : 0;
        const int excl = carry_s + warp_off + v - x;
        if (i < n) {
            off[i] = excl;
            cur[i] = excl;
        }
        const int total = warp_sums[15];
        __syncthreads();
        if (tid == 0) carry_s += total;
        __syncthreads();
    }
    if (tid == 0) off[n] = carry_s;
}

__global__ __launch_bounds__(256)
void fill_kernel(const float* __restrict__ sup_vals,
                 const int* __restrict__ sup_rows, const int* __restrict__ sup_cols) {
    const int e = blockIdx.x * 256 + threadIdx.x;
    if (e >= NUM_SUPPORT * NNZ) return;
    const int s = e / NNZ;
    const int r = sup_rows[e];
    const int c = sup_cols[e];
    const int vbits = __float_as_int(sup_vals[e]);
    const int pu = atomicAdd(&g_cur_u[s * NUM_USERS + r], 1);
    g_edges_u[(size_t)s * NNZ + pu] = make_int2(c, vbits);
    const int pv = atomicAdd(&g_cur_v[s * NUM_ITEMS + c], 1);
    g_edges_v[(size_t)s * NNZ + pv] = make_int2(r, vbits);
}

// ---------------------------------------------------------------------------
// Gather-accumulate: one warp per (dest_row, support); fused ReLU store.
// ---------------------------------------------------------------------------
__global__ __launch_bounds__(256)
void accum_kernel(const float* __restrict__ tmp,
                  float* __restrict__ z,
                  const int* __restrict__ off,
                  const int2* __restrict__ edges,
                  int nrows) {
    const int task = blockIdx.x * 8 + (threadIdx.x >> 5);
    if (task >= NUM_SUPPORT * nrows) return;
    const int s = task / nrows;
    const int row = task - s * nrows;
    const int lane = threadIdx.x & 31;

    const int* o = off + s * (nrows + 1) + row;
    const int beg = o[0];
    const int end = o[1];
    const int2* eb = edges + (size_t)s * NNZ;

    const bool act = (lane < HIDDEN / 4);
    const int coloff = s * HIDDEN + lane * 4;

    float4 acc = make_float4(0.f, 0.f, 0.f, 0.f);

    int e = beg;
    for (; e + 1 < end; e += 2) {
        const int2 e0 = eb[e];
        const int2 e1 = eb[e + 1];
        if (act) {
            const float4 t0 = *reinterpret_cast<const float4*>(
                tmp + (size_t)e0.x * OUTPUT_DIM + coloff);
            const float4 t1 = *reinterpret_cast<const float4*>(
                tmp + (size_t)e1.x * OUTPUT_DIM + coloff);
            const float v0 = __int_as_float(e0.y);
            const float v1 = __int_as_float(e1.y);
            acc.x = fmaf(v0, t0.x, acc.x); acc.y = fmaf(v0, t0.y, acc.y);
            acc.z = fmaf(v0, t0.z, acc.z); acc.w = fmaf(v0, t0.w, acc.w);
            acc.x = fmaf(v1, t1.x, acc.x); acc.y = fmaf(v1, t1.y, acc.y);
            acc.z = fmaf(v1, t1.z, acc.z); acc.w = fmaf(v1, t1.w, acc.w);
        }
    }
    if (e < end) {
        const int2 e0 = eb[e];
        if (act) {
            const float4 t0 = *reinterpret_cast<const float4*>(
                tmp + (size_t)e0.x * OUTPUT_DIM + coloff);
            const float v0 = __int_as_float(e0.y);
            acc.x = fmaf(v0, t0.x, acc.x); acc.y = fmaf(v0, t0.y, acc.y);
            acc.z = fmaf(v0, t0.z, acc.z); acc.w = fmaf(v0, t0.w, acc.w);
        }
    }

    if (act) {
        acc.x = fmaxf(acc.x, 0.f);
        acc.y = fmaxf(acc.y, 0.f);
        acc.z = fmaxf(acc.z, 0.f);
        acc.w = fmaxf(acc.w, 0.f);
        *reinterpret_cast<float4*>(z + (size_t)row * OUTPUT_DIM + coloff) = acc;
    }
}

// ---------------------------------------------------------------------------
// Streams + events created at binary load (not device-memory allocations).
// ---------------------------------------------------------------------------
static cudaStream_t g_s2 = nullptr, g_s3 = nullptr;
static cudaEvent_t g_evStart = nullptr, g_evV = nullptr, g_evF = nullptr;
static cudaEvent_t g_evAU = nullptr, g_evSU = nullptr;
static bool g_fork_ok = false;

namespace {
struct StreamInit {
    StreamInit() {
        bool ok = true;
        ok &= (cudaStreamCreateWithFlags(&g_s2, cudaStreamNonBlocking) == cudaSuccess);
        ok &= (cudaStreamCreateWithFlags(&g_s3, cudaStreamNonBlocking) == cudaSuccess);
        ok &= (cudaEventCreateWithFlags(&g_evStart, cudaEventDisableTiming) == cudaSuccess);
        ok &= (cudaEventCreateWithFlags(&g_evV, cudaEventDisableTiming) == cudaSuccess);
        ok &= (cudaEventCreateWithFlags(&g_evF, cudaEventDisableTiming) == cudaSuccess);
        ok &= (cudaEventCreateWithFlags(&g_evAU, cudaEventDisableTiming) == cudaSuccess);
        ok &= (cudaEventCreateWithFlags(&g_evSU, cudaEventDisableTiming) == cudaSuccess);
        g_fork_ok = ok;
    }
};
static StreamInit g_stream_init;
}

// ---------------------------------------------------------------------------
extern "C" void kernel_launch(void* const* d_in, const int* in_sizes, int n_in,
                              void* d_out, int out_size) {
    const float* x_u      = (const float*)d_in[0];
    const float* x_v      = (const float*)d_in[1];
    const float* W        = (const float*)d_in[2];
    const float* sup_vals = (const float*)d_in[3];
    const int*   sup_rows = (const int*)  d_in[4];
    const int*   sup_cols = (const int*)  d_in[5];

    float* z_u = (float*)d_out;
    float* z_v = z_u + (size_t)NUM_USERS * OUTPUT_DIM;

    float* tmp_u = nullptr;
    float* tmp_v = nullptr;
    __nv_bfloat16 *Bh = nullptr, *Bl = nullptr;
    __nv_bfloat16 *Ah_u = nullptr, *Al_u = nullptr, *Ah_v = nullptr, *Al_v = nullptr;
    void *cnt_u = nullptr, *cnt_v = nullptr;
    void *off_u = nullptr, *off_v = nullptr;
    void *edges_u = nullptr, *edges_v = nullptr;
    cudaGetSymbolAddress((void**)&tmp_u, g_tmp_u);
    cudaGetSymbolAddress((void**)&tmp_v, g_tmp_v);
    cudaGetSymbolAddress((void**)&Bh, g_Bh);
    cudaGetSymbolAddress((void**)&Bl, g_Bl);
    cudaGetSymbolAddress((void**)&Ah_u, g_Ah_u);
    cudaGetSymbolAddress((void**)&Al_u, g_Al_u);
    cudaGetSymbolAddress((void**)&Ah_v, g_Ah_v);
    cudaGetSymbolAddress((void**)&Al_v, g_Al_v);
    cudaGetSymbolAddress(&cnt_u, g_cnt_u);
    cudaGetSymbolAddress(&cnt_v, g_cnt_v);
    cudaGetSymbolAddress(&off_u, g_off_u);
    cudaGetSymbolAddress(&off_v, g_off_v);
    cudaGetSymbolAddress(&edges_u, g_edges_u);
    cudaGetSymbolAddress(&edges_v, g_edges_v);

    cudaFuncSetAttribute(gemm_mma_kernel,
                         cudaFuncAttributeMaxDynamicSharedMemorySize, GEMM_SMEM);

    const cudaStream_t s0 = 0;
    const cudaStream_t sCsr = g_fork_ok ? g_s2 : s0;
    const cudaStream_t sSpl = g_fork_ok ? g_s3 : s0;

    if (g_fork_ok) {
        cudaEventRecord(g_evStart, s0);
        cudaStreamWaitEvent(sCsr, g_evStart, 0);
        cudaStreamWaitEvent(sSpl, g_evStart, 0);
    }

    // --- split stream: split_u (only needs x_u; off the critical path) ---
    {
        const int n4u = NUM_USERS * INPUT_DIM / 4;
        split_a_kernel<<<(n4u + 255) / 256, 256, 0, sSpl>>>(
            (const float4*)x_u, (uint2*)Ah_u, (uint2*)Al_u, n4u);
        if (g_fork_ok) cudaEventRecord(g_evSU, sSpl);
    }

    // --- CSR stream: histogram -> scan -> fill ---
    cudaMemsetAsync(cnt_u, 0, sizeof(int) * NUM_SUPPORT * NUM_USERS, sCsr);
    cudaMemsetAsync(cnt_v, 0, sizeof(int) * NUM_SUPPORT * NUM_ITEMS, sCsr);
    {
        const int total = NUM_SUPPORT * NNZ;
        hist_kernel<<<(total + 255) / 256, 256, 0, sCsr>>>(sup_rows, sup_cols);
        scan_kernel<<<2 * NUM_SUPPORT, 512, 0, sCsr>>>();
        fill_kernel<<<(total + 255) / 256, 256, 0, sCsr>>>(sup_vals, sup_rows, sup_cols);
    }
    if (g_fork_ok) cudaEventRecord(g_evF, sCsr);

    // --- main stream: prep + small GEMM ---
    {
        const int totalB = INPUT_DIM * N_PAD;
        prep_b_kernel<<<(totalB + 255) / 256, 256, 0, s0>>>(W, Bh, Bl);
        const int n4v = NUM_ITEMS * INPUT_DIM / 4;
        split_a_kernel<<<(n4v + 255) / 256, 256, 0, s0>>>(
            (const float4*)x_v, (uint2*)Ah_v, (uint2*)Al_v, n4v);
        dim3 block(256);
        dim3 grid_v(N_PAD / 128, (NUM_ITEMS + 127) / 128);
        gemm_mma_kernel<<<grid_v, block, GEMM_SMEM, s0>>>(Ah_v, Al_v, Bh, Bl, tmp_v, NUM_ITEMS);
    }
    if (g_fork_ok) cudaEventRecord(g_evV, s0);

    // --- CSR stream: accum_u (needs tmp_v + CSR), overlaps gemm_u ---
    if (g_fork_ok) {
        cudaStreamWaitEvent(sCsr, g_evV, 0);
        const int tasks_u = NUM_SUPPORT * NUM_USERS;
        accum_kernel<<<(tasks_u + 7) / 8, 256, 0, sCsr>>>(
            tmp_v, z_u, (const int*)off_u, (const int2*)edges_u, NUM_USERS);
        cudaEventRecord(g_evAU, sCsr);
    }

    // --- main stream: big GEMM (needs split_u) ---
    if (g_fork_ok) cudaStreamWaitEvent(s0, g_evSU, 0);
    {
        dim3 block(256);
        dim3 grid_u(N_PAD / 128, (NUM_USERS + 127) / 128);
        gemm_mma_kernel<<<grid_u, block, GEMM_SMEM, s0>>>(Ah_u, Al_u, Bh, Bl, tmp_u, NUM_USERS);
    }

    // --- main stream: accum_v (needs tmp_u + CSR) ---
    if (g_fork_ok) cudaStreamWaitEvent(s0, g_evF, 0);
    {
        const int tasks_v = NUM_SUPPORT * NUM_ITEMS;
        accum_kernel<<<(tasks_v + 7) / 8, 256, 0, s0>>>(
            tmp_u, z_v, (const int*)off_v, (const int2*)edges_v, NUM_ITEMS);
    }

    if (g_fork_ok) {
        cudaStreamWaitEvent(s0, g_evAU, 0);
    } else {
        // serial fallback (streams unavailable): run accum_u last
        const int tasks_u = NUM_SUPPORT * NUM_USERS;
        accum_kernel<<<(tasks_u + 7) / 8, 256, 0, s0>>>(
            tmp_v, z_u, (const int*)off_u, (const int2*)edges_u, NUM_USERS);
    }
}

// round 17
// speedup vs baseline: 1.1341x; 1.1341x over previous
#include <cuda_runtime.h>
#include <cuda_fp16.h>
#include <cstdint>

#define NUM_USERS 50000
#define NUM_ITEMS 10000
#define NUM_SUPPORT 5
#define INPUT_DIM 512
#define OUTPUT_DIM 500
#define NNZ 400000
#define HIDDEN 100
#define N_PAD 512

// ---------------- scratch (device globals: no allocation) ----------------
__device__ float g_tmp_u[(size_t)NUM_USERS * OUTPUT_DIM];            // 100 MB
__device__ float g_tmp_v[(size_t)NUM_ITEMS * OUTPUT_DIM];            //  20 MB
__device__ __half g_Bh[(size_t)INPUT_DIM * N_PAD];                   // 0.5 MB
__device__ __half g_Ah_u[(size_t)NUM_USERS * INPUT_DIM];             // 51 MB
__device__ __half g_Al_u[(size_t)NUM_USERS * INPUT_DIM];             // 51 MB
__device__ __half g_Ah_v[(size_t)NUM_ITEMS * INPUT_DIM];             // 10 MB
__device__ __half g_Al_v[(size_t)NUM_ITEMS * INPUT_DIM];             // 10 MB

// CSR build scratch
__device__ int  g_cnt_u[NUM_SUPPORT * NUM_USERS];
__device__ int  g_cnt_v[NUM_SUPPORT * NUM_ITEMS];
__device__ int  g_off_u[NUM_SUPPORT * (NUM_USERS + 1)];
__device__ int  g_off_v[NUM_SUPPORT * (NUM_ITEMS + 1)];
__device__ int  g_cur_u[NUM_SUPPORT * NUM_USERS];
__device__ int  g_cur_v[NUM_SUPPORT * NUM_ITEMS];
__device__ int2 g_edges_u[(size_t)NUM_SUPPORT * NNZ];                // 16 MB
__device__ int2 g_edges_v[(size_t)NUM_SUPPORT * NNZ];                // 16 MB

// ---------------- GEMM tiling ----------------
// CTA 128M x 128N, 8 warps (4x2), warp tile 32x64.
// fp16 2-term split: A' = [Ah | Al] (K'=1024), B' = [Bh ; Bh].
// 16 chunks of 64 fp16; 3-stage cp.async pipeline, one barrier per chunk.
#define A_BYTES (128 * 144)
#define B_BYTES (64 * 272)
#define BUF_BYTES (A_BYTES + B_BYTES)          // 35840
#define NSTAGE 3
#define GEMM_SMEM (NSTAGE * BUF_BYTES)         // 107520
#define NCHUNK 16

__device__ __forceinline__ uint32_t smem_u32(const void* p) {
    uint32_t a;
    asm("{ .reg .u64 t; cvta.to.shared.u64 t, %1; cvt.u32.u64 %0, t; }" : "=r"(a) : "l"(p));
    return a;
}

__device__ __forceinline__ uint32_t h2_hi(float x, float y) {
    unsigned short a = __half_as_ushort(__float2half_rn(x));
    unsigned short b = __half_as_ushort(__float2half_rn(y));
    return (uint32_t)a | ((uint32_t)b << 16);
}
__device__ __forceinline__ uint32_t h2_lo(float x, float y) {
    float hx = __half2float(__float2half_rn(x));
    float hy = __half2float(__float2half_rn(y));
    unsigned short a = __half_as_ushort(__float2half_rn(x - hx));
    unsigned short b = __half_as_ushort(__float2half_rn(y - hy));
    return (uint32_t)a | ((uint32_t)b << 16);
}

__device__ __forceinline__ void ldsm_x4(uint32_t* r, uint32_t addr) {
    asm volatile("ldmatrix.sync.aligned.m8n8.x4.shared.b16 {%0,%1,%2,%3}, [%4];"
                 : "=r"(r[0]), "=r"(r[1]), "=r"(r[2]), "=r"(r[3]) : "r"(addr));
}
__device__ __forceinline__ void ldsm_x4_t(uint32_t* r, uint32_t addr) {
    asm volatile("ldmatrix.sync.aligned.m8n8.x4.trans.shared.b16 {%0,%1,%2,%3}, [%4];"
                 : "=r"(r[0]), "=r"(r[1]), "=r"(r[2]), "=r"(r[3]) : "r"(addr));
}
__device__ __forceinline__ void mma16816(float* d, const uint32_t* a,
                                         uint32_t b0, uint32_t b1) {
    asm volatile(
        "mma.sync.aligned.m16n8k16.row.col.f32.f16.f16.f32 "
        "{%0,%1,%2,%3}, {%4,%5,%6,%7}, {%8,%9}, {%0,%1,%2,%3};"
        : "+f"(d[0]), "+f"(d[1]), "+f"(d[2]), "+f"(d[3])
        : "r"(a[0]), "r"(a[1]), "r"(a[2]), "r"(a[3]), "r"(b0), "r"(b1));
}
__device__ __forceinline__ void cp16(uint32_t dst, const void* src, int srcsize) {
    asm volatile("cp.async.cg.shared.global [%0], [%1], 16, %2;"
                 :: "r"(dst), "l"(src), "r"(srcsize) : "memory");
}

// ---------------------------------------------------------------------------
// Prep: B rounded once to fp16 (zero-padded to N_PAD).
// ---------------------------------------------------------------------------
__global__ __launch_bounds__(256)
void prep_b_kernel(const float* __restrict__ W, __half* __restrict__ Bh) {
    int idx = blockIdx.x * 256 + threadIdx.x;
    if (idx >= INPUT_DIM * N_PAD) return;
    int k = idx >> 9;
    int n = idx & (N_PAD - 1);
    float w = (n < OUTPUT_DIM) ? W[(size_t)k * OUTPUT_DIM + n] : 0.0f;
    Bh[idx] = __float2half_rn(w);
}

// Pre-split A (fp32 -> fp16 hi/lo, exact 2-term). n4 = M*512/4.
__global__ __launch_bounds__(256)
void split_a_kernel(const float4* __restrict__ A,
                    uint2* __restrict__ Ah, uint2* __restrict__ Al, int n4) {
    int idx = blockIdx.x * 256 + threadIdx.x;
    if (idx >= n4) return;
    float4 v = A[idx];
    uint2 h, l;
    h.x = h2_hi(v.x, v.y); h.y = h2_hi(v.z, v.w);
    l.x = h2_lo(v.x, v.y); l.y = h2_lo(v.z, v.w);
    Ah[idx] = h;
    Al[idx] = l;
}

// ---------------------------------------------------------------------------
// GEMM: fp16 2-term pipeline (cp.async -> ldmatrix -> mma), K'=1024.
// C = (Ah + Al) @ Bh  ==  A @ round_fp16(W)
// ---------------------------------------------------------------------------
__global__ __launch_bounds__(256)
void gemm_mma_kernel(const __half* __restrict__ Ah,
                     const __half* __restrict__ Al,
                     const __half* __restrict__ Bh,
                     float* __restrict__ C, int M) {
    extern __shared__ __align__(16) char smem[];
    const uint32_t sbase = smem_u32(smem);

    const int tid  = threadIdx.x;
    const int lane = tid & 31;
    const int wid  = tid >> 5;
    const int wm   = wid & 3;
    const int wn   = wid >> 2;

    const int row0 = blockIdx.y * 128;
    const int n0   = blockIdx.x * 128;

    auto issue = [&](int c) {
        const int k0 = (c & 7) * 64;
        const __half* At = (c >= 8) ? Al : Ah;
        const uint32_t abuf = sbase + (c % NSTAGE) * BUF_BYTES;
        const uint32_t bbuf = abuf + A_BYTES;
#pragma unroll
        for (int i = 0; i < 4; i++) {
            const int s = tid + i * 256;
            const int ar = s >> 3;
            const int ao = s & 7;
            const int gm = row0 + ar;
            cp16(abuf + ar * 144 + ao * 16,
                 At + (size_t)gm * INPUT_DIM + k0 + ao * 8,
                 (gm < M) ? 16 : 0);
        }
#pragma unroll
        for (int i = 0; i < 4; i++) {
            const int s = tid + i * 256;
            const int br = s >> 4;
            const int bo = s & 15;
            cp16(bbuf + br * 272 + bo * 16,
                 Bh + (size_t)(k0 + br) * N_PAD + n0 + bo * 8, 16);
        }
        asm volatile("cp.async.commit_group;" ::: "memory");
    };

    float acc[2][8][4];
#pragma unroll
    for (int i = 0; i < 2; i++)
#pragma unroll
        for (int j = 0; j < 8; j++)
#pragma unroll
            for (int q = 0; q < 4; q++) acc[i][j][q] = 0.0f;

    const uint32_t a_lane_off =
        (uint32_t)((wm * 32 + (lane & 15)) * 144 + (lane >> 4) * 16);
    const uint32_t b_lane_off =
        (uint32_t)((lane & 15) * 272 + (wn * 64 + (lane >> 4) * 8) * 2);

    issue(0);
    issue(1);

    for (int c = 0; c < NCHUNK; c++) {
        if (c == NCHUNK - 1) {
            asm volatile("cp.async.wait_group 0;" ::: "memory");
        } else {
            asm volatile("cp.async.wait_group 1;" ::: "memory");
        }
        __syncthreads();

        if (c + 2 < NCHUNK) issue(c + 2);

        const uint32_t abase = sbase + (c % NSTAGE) * BUF_BYTES + a_lane_off;
        const uint32_t bbase = sbase + (c % NSTAGE) * BUF_BYTES + A_BYTES + b_lane_off;

#pragma unroll
        for (int ks = 0; ks < 4; ks++) {
            uint32_t a0[4], a1[4];
            ldsm_x4(a0, abase + ks * 32);
            ldsm_x4(a1, abase + 16 * 144 + ks * 32);
            uint32_t b[4][4];
#pragma unroll
            for (int q = 0; q < 4; q++)
                ldsm_x4_t(b[q], bbase + ks * 16 * 272 + q * 32);
#pragma unroll
            for (int j = 0; j < 8; j++) {
                const int q = j >> 1;
                const int h = (j & 1) * 2;
                mma16816(acc[0][j], a0, b[q][h], b[q][h + 1]);
                mma16816(acc[1][j], a1, b[q][h], b[q][h + 1]);
            }
        }
    }

    // ---- epilogue ----
#pragma unroll
    for (int i = 0; i < 2; i++) {
#pragma unroll
        for (int j = 0; j < 8; j++) {
            const int col = n0 + wn * 64 + j * 8 + (lane & 3) * 2;
            if (col >= OUTPUT_DIM) continue;
            const int r0 = row0 + wm * 32 + i * 16 + (lane >> 2);
            if (r0 < M) {
                float2 v = make_float2(acc[i][j][0], acc[i][j][1]);
                *reinterpret_cast<float2*>(&C[(size_t)r0 * OUTPUT_DIM + col]) = v;
            }
            if (r0 + 8 < M) {
                float2 v = make_float2(acc[i][j][2], acc[i][j][3]);
                *reinterpret_cast<float2*>(&C[(size_t)(r0 + 8) * OUTPUT_DIM + col]) = v;
            }
        }
    }
}

// ---------------------------------------------------------------------------
// CSR build: histogram -> scan -> fill
// ---------------------------------------------------------------------------
__global__ __launch_bounds__(256)
void hist_kernel(const int* __restrict__ sup_rows, const int* __restrict__ sup_cols) {
    const int e = blockIdx.x * 256 + threadIdx.x;
    if (e >= NUM_SUPPORT * NNZ) return;
    const int s = e / NNZ;
    atomicAdd(&g_cnt_u[s * NUM_USERS + sup_rows[e]], 1);
    atomicAdd(&g_cnt_v[s * NUM_ITEMS + sup_cols[e]], 1);
}

__global__ __launch_bounds__(512)
void scan_kernel() {
    const int aid = blockIdx.x;
    const int* cnt;
    int* off;
    int* cur;
    int n;
    if (aid < NUM_SUPPORT) {
        cnt = g_cnt_u + aid * NUM_USERS;
        off = g_off_u + aid * (NUM_USERS + 1);
        cur = g_cur_u + aid * NUM_USERS;
        n = NUM_USERS;
    } else {
        const int s = aid - NUM_SUPPORT;
        cnt = g_cnt_v + s * NUM_ITEMS;
        off = g_off_v + s * (NUM_ITEMS + 1);
        cur = g_cur_v + s * NUM_ITEMS;
        n = NUM_ITEMS;
    }

    __shared__ int warp_sums[16];
    __shared__ int carry_s;
    const int tid = threadIdx.x;
    const int lane = tid & 31;
    const int wrp = tid >> 5;
    if (tid == 0) carry_s = 0;
    __syncthreads();

    for (int base = 0; base < n; base += 512) {
        const int i = base + tid;
        const int x = (i < n) ? cnt[i] : 0;
        int v = x;
#pragma unroll
        for (int d = 1; d < 32; d <<= 1) {
            int t = __shfl_up_sync(0xffffffffu, v, d);
            if (lane >= d) v += t;
        }
        if (lane == 31) warp_sums[wrp] = v;
        __syncthreads();
        if (tid < 16) {
            int w = warp_sums[tid];
#pragma unroll
            for (int d = 1; d < 16; d <<= 1) {
                int t = __shfl_up_sync(0x0000ffffu, w, d);
                if (tid >= d) w += t;
            }
            warp_sums[tid] = w;
        }
        __syncthreads();
        const int warp_off = (wrp > 0) ? warp_sums[wrp - 1] : 0;
        const int excl = carry_s + warp_off + v - x;
        if (i < n) {
            off[i] = excl;
            cur[i] = excl;
        }
        const int total = warp_sums[15];
        __syncthreads();
        if (tid == 0) carry_s += total;
        __syncthreads();
    }
    if (tid == 0) off[n] = carry_s;
}

__global__ __launch_bounds__(256)
void fill_kernel(const float* __restrict__ sup_vals,
                 const int* __restrict__ sup_rows, const int* __restrict__ sup_cols) {
    const int e = blockIdx.x * 256 + threadIdx.x;
    if (e >= NUM_SUPPORT * NNZ) return;
    const int s = e / NNZ;
    const int r = sup_rows[e];
    const int c = sup_cols[e];
    const int vbits = __float_as_int(sup_vals[e]);
    const int pu = atomicAdd(&g_cur_u[s * NUM_USERS + r], 1);
    g_edges_u[(size_t)s * NNZ + pu] = make_int2(c, vbits);
    const int pv = atomicAdd(&g_cur_v[s * NUM_ITEMS + c], 1);
    g_edges_v[(size_t)s * NNZ + pv] = make_int2(r, vbits);
}

// ---------------------------------------------------------------------------
// Gather-accumulate: one warp per (dest_row, support); fused ReLU store.
// ---------------------------------------------------------------------------
__global__ __launch_bounds__(256)
void accum_kernel(const float* __restrict__ tmp,
                  float* __restrict__ z,
                  const int* __restrict__ off,
                  const int2* __restrict__ edges,
                  int nrows) {
    const int task = blockIdx.x * 8 + (threadIdx.x >> 5);
    if (task >= NUM_SUPPORT * nrows) return;
    const int s = task / nrows;
    const int row = task - s * nrows;
    const int lane = threadIdx.x & 31;

    const int* o = off + s * (nrows + 1) + row;
    const int beg = o[0];
    const int end = o[1];
    const int2* eb = edges + (size_t)s * NNZ;

    const bool act = (lane < HIDDEN / 4);
    const int coloff = s * HIDDEN + lane * 4;

    float4 acc = make_float4(0.f, 0.f, 0.f, 0.f);

    int e = beg;
    for (; e + 1 < end; e += 2) {
        const int2 e0 = eb[e];
        const int2 e1 = eb[e + 1];
        if (act) {
            const float4 t0 = *reinterpret_cast<const float4*>(
                tmp + (size_t)e0.x * OUTPUT_DIM + coloff);
            const float4 t1 = *reinterpret_cast<const float4*>(
                tmp + (size_t)e1.x * OUTPUT_DIM + coloff);
            const float v0 = __int_as_float(e0.y);
            const float v1 = __int_as_float(e1.y);
            acc.x = fmaf(v0, t0.x, acc.x); acc.y = fmaf(v0, t0.y, acc.y);
            acc.z = fmaf(v0, t0.z, acc.z); acc.w = fmaf(v0, t0.w, acc.w);
            acc.x = fmaf(v1, t1.x, acc.x); acc.y = fmaf(v1, t1.y, acc.y);
            acc.z = fmaf(v1, t1.z, acc.z); acc.w = fmaf(v1, t1.w, acc.w);
        }
    }
    if (e < end) {
        const int2 e0 = eb[e];
        if (act) {
            const float4 t0 = *reinterpret_cast<const float4*>(
                tmp + (size_t)e0.x * OUTPUT_DIM + coloff);
            const float v0 = __int_as_float(e0.y);
            acc.x = fmaf(v0, t0.x, acc.x); acc.y = fmaf(v0, t0.y, acc.y);
            acc.z = fmaf(v0, t0.z, acc.z); acc.w = fmaf(v0, t0.w, acc.w);
        }
    }

    if (act) {
        acc.x = fmaxf(acc.x, 0.f);
        acc.y = fmaxf(acc.y, 0.f);
        acc.z = fmaxf(acc.z, 0.f);
        acc.w = fmaxf(acc.w, 0.f);
        *reinterpret_cast<float4*>(z + (size_t)row * OUTPUT_DIM + coloff) = acc;
    }
}

// ---------------------------------------------------------------------------
// Streams + events created at binary load (not device-memory allocations).
// ---------------------------------------------------------------------------
static cudaStream_t g_s2 = nullptr, g_s3 = nullptr;
static cudaEvent_t g_evStart = nullptr, g_evPB = nullptr, g_evF = nullptr;
static cudaEvent_t g_evAU = nullptr;
static bool g_fork_ok = false;

namespace {
struct StreamInit {
    StreamInit() {
        bool ok = true;
        ok &= (cudaStreamCreateWithFlags(&g_s2, cudaStreamNonBlocking) == cudaSuccess);
        ok &= (cudaStreamCreateWithFlags(&g_s3, cudaStreamNonBlocking) == cudaSuccess);
        ok &= (cudaEventCreateWithFlags(&g_evStart, cudaEventDisableTiming) == cudaSuccess);
        ok &= (cudaEventCreateWithFlags(&g_evPB, cudaEventDisableTiming) == cudaSuccess);
        ok &= (cudaEventCreateWithFlags(&g_evF, cudaEventDisableTiming) == cudaSuccess);
        ok &= (cudaEventCreateWithFlags(&g_evAU, cudaEventDisableTiming) == cudaSuccess);
        g_fork_ok = ok;
    }
};
static StreamInit g_stream_init;
}

// ---------------------------------------------------------------------------
extern "C" void kernel_launch(void* const* d_in, const int* in_sizes, int n_in,
                              void* d_out, int out_size) {
    const float* x_u      = (const float*)d_in[0];
    const float* x_v      = (const float*)d_in[1];
    const float* W        = (const float*)d_in[2];
    const float* sup_vals = (const float*)d_in[3];
    const int*   sup_rows = (const int*)  d_in[4];
    const int*   sup_cols = (const int*)  d_in[5];

    float* z_u = (float*)d_out;
    float* z_v = z_u + (size_t)NUM_USERS * OUTPUT_DIM;

    float* tmp_u = nullptr;
    float* tmp_v = nullptr;
    __half *Bh = nullptr;
    __half *Ah_u = nullptr, *Al_u = nullptr, *Ah_v = nullptr, *Al_v = nullptr;
    void *cnt_u = nullptr, *cnt_v = nullptr;
    void *off_u = nullptr, *off_v = nullptr;
    void *edges_u = nullptr, *edges_v = nullptr;
    cudaGetSymbolAddress((void**)&tmp_u, g_tmp_u);
    cudaGetSymbolAddress((void**)&tmp_v, g_tmp_v);
    cudaGetSymbolAddress((void**)&Bh, g_Bh);
    cudaGetSymbolAddress((void**)&Ah_u, g_Ah_u);
    cudaGetSymbolAddress((void**)&Al_u, g_Al_u);
    cudaGetSymbolAddress((void**)&Ah_v, g_Ah_v);
    cudaGetSymbolAddress((void**)&Al_v, g_Al_v);
    cudaGetSymbolAddress(&cnt_u, g_cnt_u);
    cudaGetSymbolAddress(&cnt_v, g_cnt_v);
    cudaGetSymbolAddress(&off_u, g_off_u);
    cudaGetSymbolAddress(&off_v, g_off_v);
    cudaGetSymbolAddress(&edges_u, g_edges_u);
    cudaGetSymbolAddress(&edges_v, g_edges_v);

    cudaFuncSetAttribute(gemm_mma_kernel,
                         cudaFuncAttributeMaxDynamicSharedMemorySize, GEMM_SMEM);

    const cudaStream_t s0 = 0;
    const cudaStream_t sCsr = g_fork_ok ? g_s2 : s0;
    const cudaStream_t sSide = g_fork_ok ? g_s3 : s0;

    if (g_fork_ok) {
        cudaEventRecord(g_evStart, s0);
        cudaStreamWaitEvent(sCsr, g_evStart, 0);
        cudaStreamWaitEvent(sSide, g_evStart, 0);
    }

    // --- main stream: prep_b, split_u, big GEMM first ---
    {
        const int totalB = INPUT_DIM * N_PAD;
        prep_b_kernel<<<(totalB + 255) / 256, 256, 0, s0>>>(W, Bh);
        if (g_fork_ok) cudaEventRecord(g_evPB, s0);
        const int n4u = NUM_USERS * INPUT_DIM / 4;
        split_a_kernel<<<(n4u + 255) / 256, 256, 0, s0>>>(
            (const float4*)x_u, (uint2*)Ah_u, (uint2*)Al_u, n4u);
    }

    // --- side stream: split_v ---
    {
        const int n4v = NUM_ITEMS * INPUT_DIM / 4;
        split_a_kernel<<<(n4v + 255) / 256, 256, 0, sSide>>>(
            (const float4*)x_v, (uint2*)Ah_v, (uint2*)Al_v, n4v);
    }

    // --- CSR stream: histogram -> scan -> fill ---
    cudaMemsetAsync(cnt_u, 0, sizeof(int) * NUM_SUPPORT * NUM_USERS, sCsr);
    cudaMemsetAsync(cnt_v, 0, sizeof(int) * NUM_SUPPORT * NUM_ITEMS, sCsr);
    {
        const int total = NUM_SUPPORT * NNZ;
        hist_kernel<<<(total + 255) / 256, 256, 0, sCsr>>>(sup_rows, sup_cols);
        scan_kernel<<<2 * NUM_SUPPORT, 512, 0, sCsr>>>();
        fill_kernel<<<(total + 255) / 256, 256, 0, sCsr>>>(sup_vals, sup_rows, sup_cols);
    }
    if (g_fork_ok) cudaEventRecord(g_evF, sCsr);

    // --- main stream: gemm_u (prep_b + split_u on same stream) ---
    {
        dim3 block(256);
        dim3 grid_u(N_PAD / 128, (NUM_USERS + 127) / 128);
        gemm_mma_kernel<<<grid_u, block, GEMM_SMEM, s0>>>(Ah_u, Al_u, Bh, tmp_u, NUM_USERS);
    }

    // --- side stream: gemm_v (needs prep_b from s0), then accum_u ---
    if (g_fork_ok) cudaStreamWaitEvent(sSide, g_evPB, 0);
    {
        dim3 block(256);
        dim3 grid_v(N_PAD / 128, (NUM_ITEMS + 127) / 128);
        gemm_mma_kernel<<<grid_v, block, GEMM_SMEM, sSide>>>(Ah_v, Al_v, Bh, tmp_v, NUM_ITEMS);
    }
    if (g_fork_ok) cudaStreamWaitEvent(sSide, g_evF, 0);
    {
        const int tasks_u = NUM_SUPPORT * NUM_USERS;
        accum_kernel<<<(tasks_u + 7) / 8, 256, 0, sSide>>>(
            tmp_v, z_u, (const int*)off_u, (const int2*)edges_u, NUM_USERS);
        if (g_fork_ok) cudaEventRecord(g_evAU, sSide);
    }

    // --- main stream: accum_v (needs tmp_u on s0 + CSR) ---
    if (g_fork_ok) cudaStreamWaitEvent(s0, g_evF, 0);
    {
        const int tasks_v = NUM_SUPPORT * NUM_ITEMS;
        accum_kernel<<<(tasks_v + 7) / 8, 256, 0, s0>>>(
            tmp_u, z_v, (const int*)off_v, (const int2*)edges_v, NUM_ITEMS);
    }

    // --- join ---
    if (g_fork_ok) cudaStreamWaitEvent(s0, g_evAU, 0);
}